// round 3
// baseline (speedup 1.0000x reference)
#include <cuda_runtime.h>
#include <cuda_bf16.h>

// ChaosClock analytic collapse (validated R1/R2, rel_err ~2e-7):
//   logits = GRU(x[:,0,:]@Wp.T+bp, h=0) @ Wh[:, :8].T + bh
// R3: 256 CTAs x 128 threads (BPC=2) so every SM has overlapping CTAs;
// phase-1 reduction restructured from 40 dependent shuffles to 2+8.

#define BPC 2   // batches per CTA

__global__ void __launch_bounds__(128) chaos_clock_kernel(
    const float* __restrict__ x,      // (B,T,D)
    const float* __restrict__ Wp,     // (8,D)
    const float* __restrict__ bp,     // (8)
    const float* __restrict__ W_ih,   // (24,8)
    const float* __restrict__ b_ih,   // (24)
    const float* __restrict__ b_hh,   // (24)
    const float* __restrict__ Wh,     // (C,32)
    const float* __restrict__ bh,     // (C)
    float* __restrict__ out,          // (B,C)
    int T, int D, int C)
{
    const int tid  = threadIdx.x;
    const int warp = tid >> 5;
    const int lane = tid & 31;
    const int b0   = blockIdx.x * BPC;

    __shared__ float s_u[BPC][8];

    // ---- Phase 1: warp w computes u for batch b0+w ----
    if (warp < BPC) {
        const int b = b0 + warp;
        const float* xr = x + (size_t)b * T * D;   // x[b, 0, :]

        // lane = s*4 + q : lane computes partial dot for output s over
        // elements [q*16, q*16+16). D = 64.
        const int s = lane >> 2;
        const int q = lane & 3;
        const float* xp = xr + q * 16;
        const float* wp = Wp + s * D + q * 16;

        float a0 = 0.f, a1 = 0.f;
        #pragma unroll
        for (int i = 0; i < 8; ++i) {
            a0 += xp[i]     * wp[i];
            a1 += xp[i + 8] * wp[i + 8];
        }
        float acc = a0 + a1;
        // reduce across the 4 lanes of each s-group (q = low 2 bits)
        acc += __shfl_xor_sync(0xffffffffu, acc, 1);
        acc += __shfl_xor_sync(0xffffffffu, acc, 2);
        // broadcast: every lane gathers all 8 inp values
        float inp[8];
        #pragma unroll
        for (int ss = 0; ss < 8; ++ss)
            inp[ss] = __shfl_sync(0xffffffffu, acc, ss * 4) + bp[ss];

        // gi on lanes 0..23
        float gi = 0.0f;
        if (lane < 24) {
            gi = b_ih[lane];
            const float* wrow = W_ih + lane * 8;
            #pragma unroll
            for (int ss = 0; ss < 8; ++ss) gi += inp[ss] * wrow[ss];
        }
        float gz = __shfl_sync(0xffffffffu, gi, lane + 8);   // gi[8..15] -> lanes 0..7
        float gn = __shfl_sync(0xffffffffu, gi, lane + 16);  // gi[16..23] -> lanes 0..7

        if (lane < 8) {
            float r = 1.0f / (1.0f + __expf(-(gi + b_hh[lane])));
            float z = 1.0f / (1.0f + __expf(-(gz + b_hh[lane + 8])));
            float n = tanhf(gn + r * b_hh[lane + 16]);
            s_u[warp][lane] = (1.0f - z) * n;   // + z*h with h = 0
        }
    }
    __syncthreads();

    // ---- Phase 2: epilogue tile: BPC batches x C classes ----
    float u[BPC][8];
    #pragma unroll
    for (int nb = 0; nb < BPC; ++nb)
        #pragma unroll
        for (int s = 0; s < 8; ++s)
            u[nb][s] = s_u[nb][s];

    #pragma unroll 4
    for (int c = tid; c < C; c += 128) {
        const float4* w = reinterpret_cast<const float4*>(Wh + (size_t)c * 32);
        float4 w0 = w[0];
        float4 w1 = w[1];
        float bb = bh[c];
        #pragma unroll
        for (int nb = 0; nb < BPC; ++nb) {
            float acc = bb;
            acc += u[nb][0] * w0.x + u[nb][1] * w0.y + u[nb][2] * w0.z + u[nb][3] * w0.w;
            acc += u[nb][4] * w1.x + u[nb][5] * w1.y + u[nb][6] * w1.z + u[nb][7] * w1.w;
            out[(size_t)(b0 + nb) * C + c] = acc;
        }
    }
}

extern "C" void kernel_launch(void* const* d_in, const int* in_sizes, int n_in,
                              void* d_out, int out_size) {
    const float* x    = (const float*)d_in[0];
    // d_in[1] jump_rand, d_in[5] W_hh, d_in[8] Wj, d_in[9] bj: provably dead
    const float* Wp   = (const float*)d_in[2];
    const float* bp   = (const float*)d_in[3];
    const float* W_ih = (const float*)d_in[4];
    const float* b_ih = (const float*)d_in[6];
    const float* b_hh = (const float*)d_in[7];
    const float* Wh   = (const float*)d_in[10];
    const float* bh   = (const float*)d_in[11];
    float* out = (float*)d_out;

    const int C = in_sizes[11];                 // 1000
    const int B = out_size / C;                 // 512
    const int D = in_sizes[2] / 8;              // 64
    const int T = in_sizes[0] / (B * D);        // 512

    chaos_clock_kernel<<<B / BPC, 128>>>(x, Wp, bp, W_ih, b_ih, b_hh, Wh, bh, out, T, D, C);
}

// round 4
// speedup vs baseline: 1.2214x; 1.2214x over previous
#include <cuda_runtime.h>
#include <cuda_bf16.h>

// ChaosClock analytic collapse (validated, rel_err ~2e-7):
//   logits = GRU(x[:,0,:]@Wp.T+bp, h=0) @ Wh[:, :8].T + bh
// R4: back to the best config (grid=128, block=256, BPC=4), plus register
// prefetch of the full Wh/bh epilogue working set BEFORE phase-1 compute so
// the two DRAM latencies (x row, Wh tile) overlap instead of serializing.

#define BPC  4           // batches per CTA
#define CPT  4           // c-values per thread (4*256 = 1024 >= C=1000)

__global__ void __launch_bounds__(256) chaos_clock_kernel(
    const float* __restrict__ x,      // (B,T,D)
    const float* __restrict__ Wp,     // (8,D)
    const float* __restrict__ bp,     // (8)
    const float* __restrict__ W_ih,   // (24,8)
    const float* __restrict__ b_ih,   // (24)
    const float* __restrict__ b_hh,   // (24)
    const float* __restrict__ Wh,     // (C,32)
    const float* __restrict__ bh,     // (C)
    float* __restrict__ out,          // (B,C)
    int T, int D, int C)
{
    const int tid  = threadIdx.x;
    const int warp = tid >> 5;
    const int lane = tid & 31;
    const int b0   = blockIdx.x * BPC;

    __shared__ float s_u[BPC][8];

    // ---- Prefetch epilogue working set into registers (independent of u) ----
    float4 w0[CPT], w1[CPT];
    float  bb[CPT];
    bool   valid[CPT];
    #pragma unroll
    for (int k = 0; k < CPT; ++k) {
        const int c = tid + k * 256;
        valid[k] = (c < C);
        if (valid[k]) {
            const float4* w = reinterpret_cast<const float4*>(Wh + (size_t)c * 32);
            w0[k] = w[0];
            w1[k] = w[1];
            bb[k] = bh[c];
        }
    }

    // ---- Phase 1: warp w computes u for batch b0+w (overlaps with prefetch) ----
    if (warp < BPC) {
        const int b = b0 + warp;
        const float* xr = x + (size_t)b * T * D;   // x[b, 0, :]

        // lane = s*4 + q : partial dot for output s over elems [q*16, q*16+16)
        const int s = lane >> 2;
        const int q = lane & 3;
        const float* xp = xr + q * 16;
        const float* wp = Wp + s * D + q * 16;

        float a0 = 0.f, a1 = 0.f;
        #pragma unroll
        for (int i = 0; i < 8; ++i) {
            a0 += xp[i]     * wp[i];
            a1 += xp[i + 8] * wp[i + 8];
        }
        float acc = a0 + a1;
        acc += __shfl_xor_sync(0xffffffffu, acc, 1);
        acc += __shfl_xor_sync(0xffffffffu, acc, 2);

        float inp[8];
        #pragma unroll
        for (int ss = 0; ss < 8; ++ss)
            inp[ss] = __shfl_sync(0xffffffffu, acc, ss * 4) + bp[ss];

        float gi = 0.0f;
        if (lane < 24) {
            gi = b_ih[lane];
            const float* wrow = W_ih + lane * 8;
            #pragma unroll
            for (int ss = 0; ss < 8; ++ss) gi += inp[ss] * wrow[ss];
        }
        float gz = __shfl_sync(0xffffffffu, gi, lane + 8);
        float gn = __shfl_sync(0xffffffffu, gi, lane + 16);

        if (lane < 8) {
            float r = 1.0f / (1.0f + __expf(-(gi + b_hh[lane])));
            float z = 1.0f / (1.0f + __expf(-(gz + b_hh[lane + 8])));
            float n = tanhf(gn + r * b_hh[lane + 16]);
            s_u[warp][lane] = (1.0f - z) * n;   // + z*h with h = 0
        }
    }
    __syncthreads();

    float u[BPC][8];
    #pragma unroll
    for (int nb = 0; nb < BPC; ++nb)
        #pragma unroll
        for (int s = 0; s < 8; ++s)
            u[nb][s] = s_u[nb][s];

    // ---- Phase 2: pure FMA + store (all operands already in registers) ----
    #pragma unroll
    for (int k = 0; k < CPT; ++k) {
        if (!valid[k]) continue;
        const int c = tid + k * 256;
        #pragma unroll
        for (int nb = 0; nb < BPC; ++nb) {
            float acc = bb[k];
            acc += u[nb][0] * w0[k].x + u[nb][1] * w0[k].y
                 + u[nb][2] * w0[k].z + u[nb][3] * w0[k].w;
            acc += u[nb][4] * w1[k].x + u[nb][5] * w1[k].y
                 + u[nb][6] * w1[k].z + u[nb][7] * w1[k].w;
            out[(size_t)(b0 + nb) * C + c] = acc;
        }
    }
}

extern "C" void kernel_launch(void* const* d_in, const int* in_sizes, int n_in,
                              void* d_out, int out_size) {
    const float* x    = (const float*)d_in[0];
    // d_in[1] jump_rand, d_in[5] W_hh, d_in[8] Wj, d_in[9] bj: provably dead
    const float* Wp   = (const float*)d_in[2];
    const float* bp   = (const float*)d_in[3];
    const float* W_ih = (const float*)d_in[4];
    const float* b_ih = (const float*)d_in[6];
    const float* b_hh = (const float*)d_in[7];
    const float* Wh   = (const float*)d_in[10];
    const float* bh   = (const float*)d_in[11];
    float* out = (float*)d_out;

    const int C = in_sizes[11];                 // 1000
    const int B = out_size / C;                 // 512
    const int D = in_sizes[2] / 8;              // 64
    const int T = in_sizes[0] / (B * D);        // 512

    chaos_clock_kernel<<<B / BPC, 256>>>(x, Wp, bp, W_ih, b_ih, b_hh, Wh, bh, out, T, D, C);
}

// round 5
// speedup vs baseline: 1.2302x; 1.0072x over previous
#include <cuda_runtime.h>
#include <cuda_bf16.h>

// ChaosClock analytic collapse (validated, rel_err ~2e-7):
//   logits = GRU(x[:,0,:]@Wp.T+bp, h=0) @ Wh[:, :8].T + bh
// R5: R4 structure (grid=128 x 256thr, BPC=4, register prefetch) with the
// serial chain shortened: x loads issued first, fast tanh/sigmoid (no
// libdevice tanhf call), branchless prefetch tail.

#define BPC  4           // batches per CTA
#define CPT  4           // c-values per thread (4*256 = 1024 >= C=1000)

__global__ void __launch_bounds__(256) chaos_clock_kernel(
    const float* __restrict__ x,      // (B,T,D)
    const float* __restrict__ Wp,     // (8,D)
    const float* __restrict__ bp,     // (8)
    const float* __restrict__ W_ih,   // (24,8)
    const float* __restrict__ b_ih,   // (24)
    const float* __restrict__ b_hh,   // (24)
    const float* __restrict__ Wh,     // (C,32)
    const float* __restrict__ bh,     // (C)
    float* __restrict__ out,          // (B,C)
    int T, int D, int C)
{
    const int tid  = threadIdx.x;
    const int warp = tid >> 5;
    const int lane = tid & 31;
    const int b0   = blockIdx.x * BPC;

    __shared__ float s_u[BPC][8];

    // ---- Issue the x row loads FIRST (longest-latency chain edge, DRAM).
    // Warps >= BPC load a duplicate row (warp & (BPC-1)) — branchless, L1 dup.
    const int bw = warp & (BPC - 1);
    const float* xr = x + (size_t)(b0 + bw) * T * D;   // x[b, 0, :]
    const int s = lane >> 2;          // output index 0..7
    const int q = lane & 3;           // chunk index 0..3
    const float* xp = xr + q * 16;
    float xv[16];
    #pragma unroll
    for (int i = 0; i < 16; ++i) xv[i] = xp[i];

    // ---- Prefetch epilogue working set into registers (independent of u) ----
    float4 w0[CPT], w1[CPT];
    float  bb[CPT];
    #pragma unroll
    for (int k = 0; k < CPT; ++k) {
        int c = tid + k * 256;
        c = (c < C) ? c : (C - 1);    // clamp: duplicate load, store predicated later
        const float4* w = reinterpret_cast<const float4*>(Wh + (size_t)c * 32);
        w0[k] = w[0];
        w1[k] = w[1];
        bb[k] = bh[c];
    }

    // ---- Phase 1: warp w (< BPC) computes u for batch b0+w ----
    if (warp < BPC) {
        const float* wp = Wp + s * D + q * 16;
        float a0 = 0.f, a1 = 0.f;
        #pragma unroll
        for (int i = 0; i < 8; ++i) {
            a0 += xv[i]     * wp[i];
            a1 += xv[i + 8] * wp[i + 8];
        }
        float acc = a0 + a1;
        acc += __shfl_xor_sync(0xffffffffu, acc, 1);
        acc += __shfl_xor_sync(0xffffffffu, acc, 2);

        float inp[8];
        #pragma unroll
        for (int ss = 0; ss < 8; ++ss)
            inp[ss] = __shfl_sync(0xffffffffu, acc, ss * 4) + bp[ss];

        float gi = 0.0f;
        if (lane < 24) {
            gi = b_ih[lane];
            const float* wrow = W_ih + lane * 8;
            #pragma unroll
            for (int ss = 0; ss < 8; ++ss) gi += inp[ss] * wrow[ss];
        }
        float gz = __shfl_sync(0xffffffffu, gi, lane + 8);
        float gn = __shfl_sync(0xffffffffu, gi, lane + 16);

        if (lane < 8) {
            // sigmoid(a) = 1/(1+exp(-a)); tanh(a) = 2/(1+exp(-2a)) - 1
            float r = __fdividef(1.0f, 1.0f + __expf(-(gi + b_hh[lane])));
            float z = __fdividef(1.0f, 1.0f + __expf(-(gz + b_hh[lane + 8])));
            float na = gn + r * b_hh[lane + 16];
            float n = __fdividef(2.0f, 1.0f + __expf(-2.0f * na)) - 1.0f;
            s_u[warp][lane] = (1.0f - z) * n;   // + z*h with h = 0
        }
    }
    __syncthreads();

    float u[BPC][8];
    #pragma unroll
    for (int nb = 0; nb < BPC; ++nb)
        #pragma unroll
        for (int ss = 0; ss < 8; ++ss)
            u[nb][ss] = s_u[nb][ss];

    // ---- Phase 2: pure FMA + store (operands already in registers) ----
    #pragma unroll
    for (int k = 0; k < CPT; ++k) {
        const int c = tid + k * 256;
        if (c >= C) break;
        #pragma unroll
        for (int nb = 0; nb < BPC; ++nb) {
            float acc = bb[k];
            acc += u[nb][0] * w0[k].x + u[nb][1] * w0[k].y
                 + u[nb][2] * w0[k].z + u[nb][3] * w0[k].w;
            acc += u[nb][4] * w1[k].x + u[nb][5] * w1[k].y
                 + u[nb][6] * w1[k].z + u[nb][7] * w1[k].w;
            out[(size_t)(b0 + nb) * C + c] = acc;
        }
    }
}

extern "C" void kernel_launch(void* const* d_in, const int* in_sizes, int n_in,
                              void* d_out, int out_size) {
    const float* x    = (const float*)d_in[0];
    // d_in[1] jump_rand, d_in[5] W_hh, d_in[8] Wj, d_in[9] bj: provably dead
    const float* Wp   = (const float*)d_in[2];
    const float* bp   = (const float*)d_in[3];
    const float* W_ih = (const float*)d_in[4];
    const float* b_ih = (const float*)d_in[6];
    const float* b_hh = (const float*)d_in[7];
    const float* Wh   = (const float*)d_in[10];
    const float* bh   = (const float*)d_in[11];
    float* out = (float*)d_out;

    const int C = in_sizes[11];                 // 1000
    const int B = out_size / C;                 // 512
    const int D = in_sizes[2] / 8;              // 64
    const int T = in_sizes[0] / (B * D);        // 512

    chaos_clock_kernel<<<B / BPC, 256>>>(x, Wp, bp, W_ih, b_ih, b_hh, Wh, bh, out, T, D, C);
}